// round 17
// baseline (speedup 1.0000x reference)
#include <cuda_runtime.h>

#define EPSF 1e-10f
#define NBLK 592

static __device__ double g_partials[NBLK];
static __device__ unsigned g_count;   // zero-init; reset by last block each launch

__global__ void __launch_bounds__(256) loss_k(
    const float* __restrict__ preds,
    const long long* __restrict__ labs,
    const int* __restrict__ cen,
    int N, float* __restrict__ out)
{
    const int tid = threadIdx.x;
    const int nthreads = gridDim.x * blockDim.x;
    double local = 0.0;

    // grid-stride over examples; each iteration handles BOTH mod rows of one
    // example (p and p+N). They share t1 (mod1 censor window uses labs0), so
    // one window/mask computation drives two independent LDG.128 streams.
    for (int p = blockIdx.x * blockDim.x + tid; p < N; p += nthreads) {
        const int c0 = cen[p];
        const int c1 = cen[p + N];
        const long long la = labs[p];          // labs0 -> drives t1 for both
        const long long lb = labs[p + N];

        const float* p0 = preds + (size_t)p * 100;
        const float* p1 = p0 + (size_t)N * 100;

        // uncensored gathers (independent, issue early)
        if (c0 == 0) local += (double)__logf(__ldg(p0 + (int)la) + EPSF);
        if (c1 == 0) local += (double)__logf(__ldg(p1 + (int)lb) + EPSF);

        const bool d0 = (c0 == 1);
        const bool d1 = (c1 == 1);
        if (d0 | d1) {
            // s = sum_{j>=t1} p. Rows are softmax (sum==1): read the SHORTER
            // side — suffix if t1>50 (exact, small-s safe), else prefix with
            // s = 1 - prefix (s >= ~0.5 there, err ~1e-7 rel).
            const int t1 = (int)la + 1;              // 1..100, shared by both
            const bool sfx = (t1 > 50);
            const int lo4 = sfx ? (t1 >> 2) : 0;
            const int hi4 = sfx ? 25 : ((t1 + 3) >> 2);
            const int r = t1 & 3;

            const float4* q0 = (const float4*)p0;    // 400B rows -> 16B aligned
            const float4* q1 = (const float4*)p1;
            float a0 = 0.0f, a1 = 0.0f;
            #pragma unroll
            for (int k = 0; k < 13; ++k) {           // window <= 13 float4s
                const int j = lo4 + k;
                const bool in = (j < hi4);
                float4 u0 = (d0 && in) ? __ldg(q0 + j)
                                       : make_float4(0.f, 0.f, 0.f, 0.f);
                float4 u1 = (d1 && in) ? __ldg(q1 + j)
                                       : make_float4(0.f, 0.f, 0.f, 0.f);
                if (sfx) {
                    if (j == lo4 && r) {             // head mask: drop idx < t1
                        if (r > 0) { u0.x = 0.f; u1.x = 0.f; }
                        if (r > 1) { u0.y = 0.f; u1.y = 0.f; }
                        if (r > 2) { u0.z = 0.f; u1.z = 0.f; }
                    }
                } else {
                    if (j == hi4 - 1 && r) {         // tail mask: drop idx >= t1
                        if (r < 2) { u0.y = 0.f; u1.y = 0.f; }
                        if (r < 3) { u0.z = 0.f; u1.z = 0.f; }
                        u0.w = 0.f; u1.w = 0.f;      // r in 1..3 -> w dropped
                    }
                }
                a0 += (u0.x + u0.y) + (u0.z + u0.w);
                a1 += (u1.x + u1.y) + (u1.z + u1.w);
            }
            if (d0) {
                const float s = sfx ? a0 : fmaxf(1.0f - a0, 0.0f);
                local += 0.5 * (double)__logf(s + EPSF);
            }
            if (d1) {
                const float s = sfx ? a1 : fmaxf(1.0f - a1, 0.0f);
                local += 0.5 * (double)__logf(s + EPSF);
            }
        }
    }

    // block reduction (doubles)
    #pragma unroll
    for (int o = 16; o; o >>= 1)
        local += __shfl_down_sync(0xffffffffu, local, o);

    __shared__ double wsum[8];
    const int lane = tid & 31;
    const int wib = tid >> 5;
    if (lane == 0) wsum[wib] = local;
    __syncthreads();

    if (wib == 0) {
        double v = (lane < 8) ? wsum[lane] : 0.0;
        #pragma unroll
        for (int o = 4; o; o >>= 1)
            v += __shfl_down_sync(0xffffffffu, v, o);
        if (lane == 0) g_partials[blockIdx.x] = v;
    }

    // last-block-done final reduction (no second kernel)
    __shared__ bool isLast;
    if (tid == 0) {
        __threadfence();
        unsigned c = atomicAdd(&g_count, 1u);
        isLast = (c == gridDim.x - 1);
    }
    __syncthreads();

    if (isLast) {   // block-uniform
        double v = 0.0;
        for (int k = tid; k < (int)gridDim.x; k += blockDim.x)
            v += g_partials[k];
        #pragma unroll
        for (int o = 16; o; o >>= 1)
            v += __shfl_down_sync(0xffffffffu, v, o);
        if (lane == 0) wsum[wib] = v;
        __syncthreads();
        if (tid == 0) {
            double t = 0.0;
            #pragma unroll
            for (int w = 0; w < 8; ++w) t += wsum[w];
            *out = (float)(-t / (double)N);
            g_count = 0;                      // reset for next graph replay
        }
    }
}

extern "C" void kernel_launch(void* const* d_in, const int* in_sizes, int n_in,
                              void* d_out, int out_size)
{
    const float* preds = (const float*)d_in[0];        // [2, N, 100] f32
    const long long* labs = (const long long*)d_in[1]; // [2, N] i64
    const int* cen = (const int*)d_in[2];              // [2, N] i32

    const int rows = in_sizes[1];      // 2*N
    const int N = rows / 2;

    loss_k<<<NBLK, 256>>>(preds, labs, cen, N, (float*)d_out);
}